// round 11
// baseline (speedup 1.0000x reference)
#include <cuda_runtime.h>
#include <cuda_bf16.h>
#include <cstdint>
#include <cstddef>

// ---------------------------------------------------------------------------
// Problem constants
// ---------------------------------------------------------------------------
#define TOK   16384      // B*L
#define DIM   1024       // D
#define NHEAD 16
#define HDIM  64

// GEMM tiling (mma.sync m16n8k16 bf16, fp32 accum)
#define TM 128
#define TN 128
#define KC 64                     // K elems per smem chunk (128B rows)
#define KTOT   (3 * DIM)          // 3072: [Ah|Al|Ah] x [Bh|Bh|Bl] split-K
#define NCHUNKS (KTOT / KC)       // 48
#define STAGES 3
#define ASTAGE (TM * KC * 2)      // 16384 B
#define BSTAGE (TN * KC * 2)      // 16384 B
#define STAGE_B (ASTAGE + BSTAGE) // 32768 B
#define SMEM_SZ (STAGES * STAGE_B) // 98304 B

// ---------------------------------------------------------------------------
// Scratch (__device__ arrays; cudaMalloc forbidden)
// ---------------------------------------------------------------------------
__device__ float          g_Q [(size_t)TOK * DIM];
__device__ float          g_K [(size_t)TOK * DIM];
__device__ float          g_V [(size_t)TOK * DIM];
__device__ float          g_Y [(size_t)TOK * DIM];
__device__ __nv_bfloat16  g_Ahi[(size_t)TOK * DIM];
__device__ __nv_bfloat16  g_Alo[(size_t)TOK * DIM];
__device__ __nv_bfloat16  g_Wthi[4ull * DIM * DIM];   // W^T hi per weight
__device__ __nv_bfloat16  g_Wtlo[4ull * DIM * DIM];   // W^T lo per weight

// ---------------------------------------------------------------------------
// Helpers
// ---------------------------------------------------------------------------
__device__ __forceinline__ uint32_t smem_u32(const void* p) {
    uint32_t a;
    asm("{ .reg .u64 t; cvta.to.shared.u64 t, %1; cvt.u32.u64 %0, t; }"
        : "=r"(a) : "l"(p));
    return a;
}

#define CP_ASYNC16(dst, src) \
    asm volatile("cp.async.cg.shared.global [%0], [%1], 16;" \
                 :: "r"(dst), "l"(src) : "memory")
#define CP_COMMIT() asm volatile("cp.async.commit_group;" ::: "memory")
#define CP_WAIT1()  asm volatile("cp.async.wait_group 1;" ::: "memory")

#define LDMATRIX_X4(r0, r1, r2, r3, addr) \
    asm volatile("ldmatrix.sync.aligned.m8n8.x4.shared.b16 {%0,%1,%2,%3}, [%4];" \
                 : "=r"(r0), "=r"(r1), "=r"(r2), "=r"(r3) : "r"(addr) : "memory")

#define MMA16816(c, a, b0, b1) \
    asm volatile("mma.sync.aligned.m16n8k16.row.col.f32.bf16.bf16.f32 " \
                 "{%0,%1,%2,%3},{%4,%5,%6,%7},{%8,%9},{%0,%1,%2,%3};" \
                 : "+f"((c)[0]), "+f"((c)[1]), "+f"((c)[2]), "+f"((c)[3]) \
                 : "r"((a)[0]), "r"((a)[1]), "r"((a)[2]), "r"((a)[3]), \
                   "r"(b0), "r"(b1))

// ---------------------------------------------------------------------------
// Conversion kernels: fp32 -> (hi, lo) bf16 split
// ---------------------------------------------------------------------------
__global__ __launch_bounds__(256) void fsplit(
    const float* __restrict__ in, __nv_bfloat16* __restrict__ hi,
    __nv_bfloat16* __restrict__ lo, int n)
{
    int i = blockIdx.x * 256 + threadIdx.x;
    if (i < n) {
        float v = in[i];
        __nv_bfloat16 h = __float2bfloat16(v);
        hi[i] = h;
        lo[i] = __float2bfloat16(v - __bfloat162float(h));
    }
}

// W [K][N] fp32 -> W^T [N][K] split bf16
__global__ __launch_bounds__(256) void wsplit_t(
    const float* __restrict__ W, __nv_bfloat16* __restrict__ hi,
    __nv_bfloat16* __restrict__ lo)
{
    int i = blockIdx.x * 256 + threadIdx.x;   // i = k*DIM + n, coalesced read
    int k = i >> 10, n = i & 1023;
    float v = W[i];
    __nv_bfloat16 h = __float2bfloat16(v);
    hi[n * DIM + k] = h;
    lo[n * DIM + k] = __float2bfloat16(v - __bfloat162float(h));
}

// ---------------------------------------------------------------------------
// Stage loader: A tile (TM x KC) + B tile (TN x KC), bf16, 128B rows,
// XOR swizzle (16B chunk index ^= row&7). 256 threads, 8 cp.async each.
// ---------------------------------------------------------------------------
__device__ __forceinline__ void ldst_stage(
    uint32_t stA, uint32_t stB,
    const __nv_bfloat16* __restrict__ Asrc,
    const __nv_bfloat16* __restrict__ Bsrc,
    int kk, int m0, int n0, int tid)
{
#pragma unroll
    for (int p = 0; p < 4; p++) {
        int q   = tid + p * 256;      // 0..1023
        int row = q >> 3, c = q & 7;
        uint32_t sw = (uint32_t)(row * 128 + ((c ^ (row & 7)) << 4));
        const void* gA = Asrc + (size_t)(m0 + row) * DIM + kk + c * 8;
        const void* gB = Bsrc + (size_t)(n0 + row) * DIM + kk + c * 8;
        CP_ASYNC16(stA + sw, gA);
        CP_ASYNC16(stB + sw, gB);
    }
    CP_COMMIT();
}

// ---------------------------------------------------------------------------
// GEMM: C[m,n] = sum_k' A'[m,k'] * Bt'[n,k'] + bias[n]
// A' = [Ahi | Alo | Ahi], Bt' = [Bhi | Bhi | Blo] along K' = 3072.
// grid (N/TN, M/TM), 256 threads (8 warps: 2 in M x 4 in N, 64x32 each).
// ---------------------------------------------------------------------------
__global__ __launch_bounds__(256) void gemm_mma(
    const __nv_bfloat16* __restrict__ Ahi, const __nv_bfloat16* __restrict__ Alo,
    const __nv_bfloat16* __restrict__ Bhi, const __nv_bfloat16* __restrict__ Blo,
    const float* __restrict__ bias, float* __restrict__ C)
{
    extern __shared__ char smem[];
    __shared__ float sbias[TN];
    const uint32_t sb = smem_u32(smem);
    const int tid = threadIdx.x, lane = tid & 31, wid = tid >> 5;
    const int wm = wid & 1, wn = wid >> 1;
    const int m0 = blockIdx.y * TM, n0 = blockIdx.x * TN;

    if (tid < TN) sbias[tid] = bias[n0 + tid];

    // prologue: stages for chunks 0..STAGES-2 (all phase 0)
#pragma unroll
    for (int c = 0; c < STAGES - 1; c++) {
        uint32_t st = sb + c * STAGE_B;
        ldst_stage(st, st + ASTAGE, Ahi, Bhi, c * KC, m0, n0, tid);
    }

    float acc[4][4][4];
#pragma unroll
    for (int i = 0; i < 4; i++)
#pragma unroll
        for (int j = 0; j < 4; j++)
#pragma unroll
            for (int r = 0; r < 4; r++) acc[i][j][r] = 0.0f;

    // per-thread ldmatrix invariants
    const int rowoffA = ((lane >> 3) & 1) * 8 + (lane & 7);  // x4 mats: r0-7 klo, r8-15 klo, r0-7 khi, r8-15 khi
    const int khalfA  = lane >> 4;
    const int rowoffB = ((lane >> 4) & 1) * 8 + (lane & 7);  // x4 mats: n0-7 klo, n0-7 khi, n8-15 klo, n8-15 khi
    const int khalfB  = (lane >> 3) & 1;
    const int s       = lane & 7;                            // swizzle key (= row&7 for all tiles)
    uint32_t offA[4], offB[2];
#pragma unroll
    for (int i = 0; i < 4; i++) offA[i] = (uint32_t)((wm * 64 + i * 16 + rowoffA) * 128);
#pragma unroll
    for (int j = 0; j < 2; j++) offB[j] = (uint32_t)(ASTAGE + (wn * 32 + j * 16 + rowoffB) * 128);

#pragma unroll 1
    for (int c = 0; c < NCHUNKS; c++) {
        CP_WAIT1();
        __syncthreads();

        // issue load for chunk c + STAGES-1
        const int cn = c + STAGES - 1;
        if (cn < NCHUNKS) {
            const int ph = cn >> 4;
            const __nv_bfloat16* As_ = (ph == 1) ? Alo : Ahi;
            const __nv_bfloat16* Bs_ = (ph == 2) ? Blo : Bhi;
            uint32_t st = sb + (cn % STAGES) * STAGE_B;
            ldst_stage(st, st + ASTAGE, As_, Bs_, (cn & 15) * KC, m0, n0, tid);
        } else {
            CP_COMMIT();   // keep group accounting aligned
        }

        const uint32_t stage = sb + (c % STAGES) * STAGE_B;
#pragma unroll
        for (int k16 = 0; k16 < KC / 16; k16++) {
            uint32_t af[4][4], bf[2][4];
            const uint32_t ca = (uint32_t)(((2 * k16 + khalfA) ^ s) << 4);
            const uint32_t cb = (uint32_t)(((2 * k16 + khalfB) ^ s) << 4);
#pragma unroll
            for (int i = 0; i < 4; i++)
                LDMATRIX_X4(af[i][0], af[i][1], af[i][2], af[i][3],
                            stage + offA[i] + ca);
#pragma unroll
            for (int j = 0; j < 2; j++)
                LDMATRIX_X4(bf[j][0], bf[j][1], bf[j][2], bf[j][3],
                            stage + offB[j] + cb);
#pragma unroll
            for (int i = 0; i < 4; i++)
#pragma unroll
                for (int j = 0; j < 4; j++)
                    MMA16816(acc[i][j], af[i],
                             bf[j >> 1][(j & 1) * 2], bf[j >> 1][(j & 1) * 2 + 1]);
        }
    }

    // epilogue: frag (i,j): rows m0+wm*64+i*16+(lane>>2)(+8), cols wn*32+j*8+(lane&3)*2
    const int mrow = lane >> 2;
    const int ncol = (lane & 3) * 2;
#pragma unroll
    for (int i = 0; i < 4; i++) {
        const int r0 = m0 + wm * 64 + i * 16 + mrow;
#pragma unroll
        for (int j = 0; j < 4; j++) {
            const int col = wn * 32 + j * 8 + ncol;
            const float bx = sbias[col], by = sbias[col + 1];
            float2 v0 = { acc[i][j][0] + bx, acc[i][j][1] + by };
            float2 v1 = { acc[i][j][2] + bx, acc[i][j][3] + by };
            *(float2*)(C + (size_t)r0 * DIM + n0 + col)       = v0;
            *(float2*)(C + (size_t)(r0 + 8) * DIM + n0 + col) = v1;
        }
    }
}

// ---------------------------------------------------------------------------
// Per-token attention (fp32, exact reference semantics).
// q[i][j] = qvec[i*16+j] (head_dim-major). s[i][k] = dot16/4 + 1e-6.
// keep iff (k<=i) && (s != 0)  [jnp.where(tril(values)): nonzero-as-true]
// ---------------------------------------------------------------------------
__global__ __launch_bounds__(64) void attn_kernel(
    const float* __restrict__ Q, const float* __restrict__ K,
    const float* __restrict__ V, float* __restrict__ Y)
{
    __shared__ float qs[HDIM][NHEAD];
    __shared__ float ks[HDIM][NHEAD];
    __shared__ float vs[HDIM][NHEAD];

    const size_t base = (size_t)blockIdx.x * DIM;
    const int tid = threadIdx.x;

    const float4* q4 = (const float4*)(Q + base);
    const float4* k4 = (const float4*)(K + base);
    const float4* v4 = (const float4*)(V + base);
#pragma unroll
    for (int i = 0; i < 4; i++) {
        const int idx = tid + i * 64;
        ((float4*)qs)[idx] = q4[idx];
        ((float4*)ks)[idx] = k4[idx];
        ((float4*)vs)[idx] = v4[idx];
    }
    __syncthreads();

    float qr[NHEAD];
#pragma unroll
    for (int j = 0; j < NHEAD; j++) qr[j] = qs[tid][j];

    const float NEG_INF = __int_as_float(0xff800000);
    float s[HDIM];
    float mx = NEG_INF;
#pragma unroll
    for (int kk = 0; kk < HDIM; kk++) {
        float d = 0.0f;
#pragma unroll
        for (int j = 0; j < NHEAD; j++) d = fmaf(qr[j], ks[kk][j], d);
        d = d * 0.25f + 1e-6f;
        const bool valid = (kk <= tid) && (d != 0.0f);
        s[kk] = valid ? d : NEG_INF;
        if (valid) mx = fmaxf(mx, d);
    }

    float sum = 0.0f;
#pragma unroll
    for (int kk = 0; kk < HDIM; kk++) {
        float p = __expf(s[kk] - mx);
        sum += p;
        s[kk] = p;
    }
    const float inv = 1.0f / sum;

    float yacc[NHEAD];
#pragma unroll
    for (int j = 0; j < NHEAD; j++) yacc[j] = 0.0f;
#pragma unroll
    for (int kk = 0; kk < HDIM; kk++) {
        const float p = s[kk];
#pragma unroll
        for (int j = 0; j < NHEAD; j++)
            yacc[j] = fmaf(p, vs[kk][j], yacc[j]);
    }

    float* yout = Y + base + tid * NHEAD;
#pragma unroll
    for (int j4 = 0; j4 < 4; j4++) {
        float4 o;
        o.x = yacc[j4 * 4 + 0] * inv;
        o.y = yacc[j4 * 4 + 1] * inv;
        o.z = yacc[j4 * 4 + 2] * inv;
        o.w = yacc[j4 * 4 + 3] * inv;
        *(float4*)&yout[j4 * 4] = o;
    }
}

// ---------------------------------------------------------------------------
// Launch
// ---------------------------------------------------------------------------
extern "C" void kernel_launch(void* const* d_in, const int* in_sizes, int n_in,
                              void* d_out, int out_size)
{
    const float* x  = (const float*)d_in[0];
    const float* Wq = (const float*)d_in[1];
    const float* bq = (const float*)d_in[2];
    const float* Wk = (const float*)d_in[3];
    const float* bk = (const float*)d_in[4];
    const float* Wv = (const float*)d_in[5];
    const float* bv = (const float*)d_in[6];
    const float* Wo = (const float*)d_in[7];
    const float* bo = (const float*)d_in[8];
    float* out = (float*)d_out;

    float *Qp, *Kp, *Vp, *Yp;
    __nv_bfloat16 *Ahi, *Alo, *Whi, *Wlo;
    cudaGetSymbolAddress((void**)&Qp,  g_Q);
    cudaGetSymbolAddress((void**)&Kp,  g_K);
    cudaGetSymbolAddress((void**)&Vp,  g_V);
    cudaGetSymbolAddress((void**)&Yp,  g_Y);
    cudaGetSymbolAddress((void**)&Ahi, g_Ahi);
    cudaGetSymbolAddress((void**)&Alo, g_Alo);
    cudaGetSymbolAddress((void**)&Whi, g_Wthi);
    cudaGetSymbolAddress((void**)&Wlo, g_Wtlo);

    cudaFuncSetAttribute(gemm_mma, cudaFuncAttributeMaxDynamicSharedMemorySize,
                         SMEM_SZ);

    const int WN = DIM * DIM;
    const size_t WS = (size_t)DIM * DIM;

    // 1) split/transpose weights, split x
    wsplit_t<<<WN / 256, 256>>>(Wq, Whi + 0 * WS, Wlo + 0 * WS);
    wsplit_t<<<WN / 256, 256>>>(Wk, Whi + 1 * WS, Wlo + 1 * WS);
    wsplit_t<<<WN / 256, 256>>>(Wv, Whi + 2 * WS, Wlo + 2 * WS);
    wsplit_t<<<WN / 256, 256>>>(Wo, Whi + 3 * WS, Wlo + 3 * WS);
    fsplit<<<(TOK * DIM) / 256, 256>>>(x, Ahi, Alo, TOK * DIM);

    // 2) QKV projections
    dim3 grid(DIM / TN, TOK / TM);   // (8, 128)
    gemm_mma<<<grid, 256, SMEM_SZ>>>(Ahi, Alo, Whi + 0 * WS, Wlo + 0 * WS, bq, Qp);
    gemm_mma<<<grid, 256, SMEM_SZ>>>(Ahi, Alo, Whi + 1 * WS, Wlo + 1 * WS, bk, Kp);
    gemm_mma<<<grid, 256, SMEM_SZ>>>(Ahi, Alo, Whi + 2 * WS, Wlo + 2 * WS, bv, Vp);

    // 3) attention
    attn_kernel<<<TOK, 64>>>(Qp, Kp, Vp, Yp);

    // 4) output projection
    fsplit<<<(TOK * DIM) / 256, 256>>>(Yp, Ahi, Alo, TOK * DIM);
    gemm_mma<<<grid, 256, SMEM_SZ>>>(Ahi, Alo, Whi + 3 * WS, Wlo + 3 * WS, bo, out);
}

// round 13
// speedup vs baseline: 1.0155x; 1.0155x over previous
#include <cuda_runtime.h>
#include <cuda_bf16.h>
#include <cstdint>
#include <cstddef>

// ---------------------------------------------------------------------------
// Problem constants
// ---------------------------------------------------------------------------
#define TOK   16384      // B*L
#define DIM   1024       // D
#define NHEAD 16
#define HDIM  64

// GEMM tiling (mma.sync m16n8k16 bf16, fp32 accum)
// Per-chunk 4-tile form: each chunk holds Ah, Al, Bh, Bl tiles for KC columns;
// the 3 split terms (AhBh + AlBh + AhBl) are issued per k16 with shared frags.
#define TM 128
#define TN 128
#define KC 64                      // K elems per chunk (128B rows)
#define NCHUNKS (DIM / KC)         // 16
#define STAGES 3
#define TILE_B  (TM * KC * 2)      // 16384 B (one 128x64 bf16 tile)
#define STAGE_B (4 * TILE_B)       // 65536 B (Ah, Al, Bh, Bl)
#define SMEM_SZ (STAGES * STAGE_B) // 196608 B

// ---------------------------------------------------------------------------
// Scratch (__device__ arrays; cudaMalloc forbidden)
// ---------------------------------------------------------------------------
__device__ float          g_Q [(size_t)TOK * DIM];
__device__ float          g_K [(size_t)TOK * DIM];
__device__ float          g_V [(size_t)TOK * DIM];
__device__ float          g_Y [(size_t)TOK * DIM];
__device__ __nv_bfloat16  g_Ahi[(size_t)TOK * DIM];
__device__ __nv_bfloat16  g_Alo[(size_t)TOK * DIM];
__device__ __nv_bfloat16  g_Wthi[4ull * DIM * DIM];   // W^T hi per weight
__device__ __nv_bfloat16  g_Wtlo[4ull * DIM * DIM];   // W^T lo per weight

// ---------------------------------------------------------------------------
// Helpers
// ---------------------------------------------------------------------------
__device__ __forceinline__ uint32_t smem_u32(const void* p) {
    uint32_t a;
    asm("{ .reg .u64 t; cvta.to.shared.u64 t, %1; cvt.u32.u64 %0, t; }"
        : "=r"(a) : "l"(p));
    return a;
}

#define CP_ASYNC16(dst, src) \
    asm volatile("cp.async.cg.shared.global [%0], [%1], 16;" \
                 :: "r"(dst), "l"(src) : "memory")
#define CP_COMMIT() asm volatile("cp.async.commit_group;" ::: "memory")
#define CP_WAIT1()  asm volatile("cp.async.wait_group 1;" ::: "memory")

#define LDMATRIX_X4(r0, r1, r2, r3, addr) \
    asm volatile("ldmatrix.sync.aligned.m8n8.x4.shared.b16 {%0,%1,%2,%3}, [%4];" \
                 : "=r"(r0), "=r"(r1), "=r"(r2), "=r"(r3) : "r"(addr) : "memory")

#define MMA16816(c, a, b0, b1) \
    asm volatile("mma.sync.aligned.m16n8k16.row.col.f32.bf16.bf16.f32 " \
                 "{%0,%1,%2,%3},{%4,%5,%6,%7},{%8,%9},{%0,%1,%2,%3};" \
                 : "+f"((c)[0]), "+f"((c)[1]), "+f"((c)[2]), "+f"((c)[3]) \
                 : "r"((a)[0]), "r"((a)[1]), "r"((a)[2]), "r"((a)[3]), \
                   "r"(b0), "r"(b1))

// ---------------------------------------------------------------------------
// Conversion kernels: fp32 -> (hi, lo) bf16 split
// ---------------------------------------------------------------------------
__global__ __launch_bounds__(256) void fsplit(
    const float* __restrict__ in, __nv_bfloat16* __restrict__ hi,
    __nv_bfloat16* __restrict__ lo, int n)
{
    int i = blockIdx.x * 256 + threadIdx.x;
    if (i < n) {
        float v = in[i];
        __nv_bfloat16 h = __float2bfloat16(v);
        hi[i] = h;
        lo[i] = __float2bfloat16(v - __bfloat162float(h));
    }
}

// All four W [K][N] fp32 -> W^T [N][K] split bf16, one launch.
// idx in [0, 4*DIM*DIM); weight w = idx>>20, element i = idx & (DIM*DIM-1).
__global__ __launch_bounds__(256) void wsplit4(
    const float* __restrict__ W0, const float* __restrict__ W1,
    const float* __restrict__ W2, const float* __restrict__ W3,
    __nv_bfloat16* __restrict__ hi, __nv_bfloat16* __restrict__ lo)
{
    int idx = blockIdx.x * 256 + threadIdx.x;
    int w = idx >> 20;                 // DIM*DIM = 1M elements per weight
    int i = idx & ((DIM * DIM) - 1);
    const float* W = (w == 0) ? W0 : (w == 1) ? W1 : (w == 2) ? W2 : W3;
    int k = i >> 10, n = i & 1023;     // i = k*DIM + n (coalesced read)
    float v = W[i];
    __nv_bfloat16 h = __float2bfloat16(v);
    size_t o = (size_t)w * (DIM * DIM) + (size_t)n * DIM + k;
    hi[o] = h;
    lo[o] = __float2bfloat16(v - __bfloat162float(h));
}

// ---------------------------------------------------------------------------
// Stage loader: 4 tiles (Ah, Al, Bh, Bl), each TM x KC bf16, 128B rows,
// XOR swizzle (16B chunk index ^= row&7). 256 threads, 16 cp.async each.
// ---------------------------------------------------------------------------
__device__ __forceinline__ void ldst_stage4(
    uint32_t st,
    const __nv_bfloat16* __restrict__ Ahi, const __nv_bfloat16* __restrict__ Alo,
    const __nv_bfloat16* __restrict__ Bhi, const __nv_bfloat16* __restrict__ Blo,
    int kk, int m0, int n0, int tid)
{
#pragma unroll
    for (int p = 0; p < 4; p++) {
        int q   = tid + p * 256;      // 0..1023
        int row = q >> 3, c = q & 7;
        uint32_t sw = (uint32_t)(row * 128 + ((c ^ (row & 7)) << 4));
        size_t aoff = (size_t)(m0 + row) * DIM + kk + c * 8;
        size_t boff = (size_t)(n0 + row) * DIM + kk + c * 8;
        CP_ASYNC16(st + 0 * TILE_B + sw, Ahi + aoff);
        CP_ASYNC16(st + 1 * TILE_B + sw, Alo + aoff);
        CP_ASYNC16(st + 2 * TILE_B + sw, Bhi + boff);
        CP_ASYNC16(st + 3 * TILE_B + sw, Blo + boff);
    }
    CP_COMMIT();
}

// ---------------------------------------------------------------------------
// GEMM: C = A x B^T + bias, bf16x3 split: AhBh + AlBh + AhBl, fp32 accum.
// grid (N/TN, M/TM), 256 threads (8 warps: 2 in M x 4 in N, 64x32 each).
// ---------------------------------------------------------------------------
__global__ __launch_bounds__(256) void gemm_mma(
    const __nv_bfloat16* __restrict__ Ahi, const __nv_bfloat16* __restrict__ Alo,
    const __nv_bfloat16* __restrict__ Bhi, const __nv_bfloat16* __restrict__ Blo,
    const float* __restrict__ bias, float* __restrict__ C)
{
    extern __shared__ char smem[];
    __shared__ float sbias[TN];
    const uint32_t sb = smem_u32(smem);
    const int tid = threadIdx.x, lane = tid & 31, wid = tid >> 5;
    const int wm = wid & 1, wn = wid >> 1;
    const int m0 = blockIdx.y * TM, n0 = blockIdx.x * TN;

    if (tid < TN) sbias[tid] = bias[n0 + tid];

    // prologue: chunks 0..STAGES-2
#pragma unroll
    for (int c = 0; c < STAGES - 1; c++)
        ldst_stage4(sb + c * STAGE_B, Ahi, Alo, Bhi, Blo, c * KC, m0, n0, tid);

    float acc[4][4][4];
#pragma unroll
    for (int i = 0; i < 4; i++)
#pragma unroll
        for (int j = 0; j < 4; j++)
#pragma unroll
            for (int r = 0; r < 4; r++) acc[i][j][r] = 0.0f;

    // per-thread ldmatrix invariants (same fragment maps as validated R11)
    const int rowoffA = ((lane >> 3) & 1) * 8 + (lane & 7);
    const int khalfA  = lane >> 4;
    const int rowoffB = ((lane >> 4) & 1) * 8 + (lane & 7);
    const int khalfB  = (lane >> 3) & 1;
    const int s       = lane & 7;
    uint32_t offA[4], offB[2];
#pragma unroll
    for (int i = 0; i < 4; i++) offA[i] = (uint32_t)((wm * 64 + i * 16 + rowoffA) * 128);
#pragma unroll
    for (int j = 0; j < 2; j++) offB[j] = (uint32_t)((wn * 32 + j * 16 + rowoffB) * 128);

#pragma unroll 1
    for (int c = 0; c < NCHUNKS; c++) {
        CP_WAIT1();
        __syncthreads();   // chunk c resident; all warps done with stage (c+2)%3's prior reads

        const int cn = c + STAGES - 1;
        if (cn < NCHUNKS)
            ldst_stage4(sb + (cn % STAGES) * STAGE_B, Ahi, Alo, Bhi, Blo,
                        cn * KC, m0, n0, tid);
        else
            CP_COMMIT();   // keep group accounting aligned

        const uint32_t stage = sb + (c % STAGES) * STAGE_B;
#pragma unroll
        for (int k16 = 0; k16 < KC / 16; k16++) {
            const uint32_t ca = (uint32_t)(((2 * k16 + khalfA) ^ s) << 4);
            const uint32_t cb = (uint32_t)(((2 * k16 + khalfB) ^ s) << 4);
            uint32_t afh[4][4], afl[4][4], bfh[2][4], bfl[2][4];
#pragma unroll
            for (int i = 0; i < 4; i++) {
                LDMATRIX_X4(afh[i][0], afh[i][1], afh[i][2], afh[i][3],
                            stage + 0 * TILE_B + offA[i] + ca);
                LDMATRIX_X4(afl[i][0], afl[i][1], afl[i][2], afl[i][3],
                            stage + 1 * TILE_B + offA[i] + ca);
            }
#pragma unroll
            for (int j = 0; j < 2; j++) {
                LDMATRIX_X4(bfh[j][0], bfh[j][1], bfh[j][2], bfh[j][3],
                            stage + 2 * TILE_B + offB[j] + cb);
                LDMATRIX_X4(bfl[j][0], bfl[j][1], bfl[j][2], bfl[j][3],
                            stage + 3 * TILE_B + offB[j] + cb);
            }
#pragma unroll
            for (int i = 0; i < 4; i++)
#pragma unroll
                for (int j = 0; j < 4; j++) {
                    const uint32_t b0h = bfh[j >> 1][(j & 1) * 2];
                    const uint32_t b1h = bfh[j >> 1][(j & 1) * 2 + 1];
                    const uint32_t b0l = bfl[j >> 1][(j & 1) * 2];
                    const uint32_t b1l = bfl[j >> 1][(j & 1) * 2 + 1];
                    MMA16816(acc[i][j], afh[i], b0h, b1h);   // Ah*Bh
                    MMA16816(acc[i][j], afl[i], b0h, b1h);   // Al*Bh
                    MMA16816(acc[i][j], afh[i], b0l, b1l);   // Ah*Bl
                }
        }
    }

    // epilogue: frag (i,j): rows m0+wm*64+i*16+(lane>>2)(+8), cols wn*32+j*8+(lane&3)*2
    const int mrow = lane >> 2;
    const int ncol = (lane & 3) * 2;
#pragma unroll
    for (int i = 0; i < 4; i++) {
        const int r0 = m0 + wm * 64 + i * 16 + mrow;
#pragma unroll
        for (int j = 0; j < 4; j++) {
            const int col = wn * 32 + j * 8 + ncol;
            const float bx = sbias[col], by = sbias[col + 1];
            float2 v0 = { acc[i][j][0] + bx, acc[i][j][1] + by };
            float2 v1 = { acc[i][j][2] + bx, acc[i][j][3] + by };
            *(float2*)(C + (size_t)r0 * DIM + n0 + col)       = v0;
            *(float2*)(C + (size_t)(r0 + 8) * DIM + n0 + col) = v1;
        }
    }
}

// ---------------------------------------------------------------------------
// Per-token attention (fp32, exact reference semantics).
// q[i][j] = qvec[i*16+j] (head_dim-major). s[i][k] = dot16/4 + 1e-6.
// keep iff (k<=i) && (s != 0)  [jnp.where(tril(values)): nonzero-as-true]
// ---------------------------------------------------------------------------
__global__ __launch_bounds__(64) void attn_kernel(
    const float* __restrict__ Q, const float* __restrict__ K,
    const float* __restrict__ V, float* __restrict__ Y)
{
    __shared__ float qs[HDIM][NHEAD];
    __shared__ float ks[HDIM][NHEAD];
    __shared__ float vs[HDIM][NHEAD];

    const size_t base = (size_t)blockIdx.x * DIM;
    const int tid = threadIdx.x;

    const float4* q4 = (const float4*)(Q + base);
    const float4* k4 = (const float4*)(K + base);
    const float4* v4 = (const float4*)(V + base);
#pragma unroll
    for (int i = 0; i < 4; i++) {
        const int idx = tid + i * 64;
        ((float4*)qs)[idx] = q4[idx];
        ((float4*)ks)[idx] = k4[idx];
        ((float4*)vs)[idx] = v4[idx];
    }
    __syncthreads();

    float qr[NHEAD];
#pragma unroll
    for (int j = 0; j < NHEAD; j++) qr[j] = qs[tid][j];

    const float NEG_INF = __int_as_float(0xff800000);
    float s[HDIM];
    float mx = NEG_INF;
#pragma unroll
    for (int kk = 0; kk < HDIM; kk++) {
        float d = 0.0f;
#pragma unroll
        for (int j = 0; j < NHEAD; j++) d = fmaf(qr[j], ks[kk][j], d);
        d = d * 0.25f + 1e-6f;
        const bool valid = (kk <= tid) && (d != 0.0f);
        s[kk] = valid ? d : NEG_INF;
        if (valid) mx = fmaxf(mx, d);
    }

    float sum = 0.0f;
#pragma unroll
    for (int kk = 0; kk < HDIM; kk++) {
        float p = __expf(s[kk] - mx);
        sum += p;
        s[kk] = p;
    }
    const float inv = 1.0f / sum;

    float yacc[NHEAD];
#pragma unroll
    for (int j = 0; j < NHEAD; j++) yacc[j] = 0.0f;
#pragma unroll
    for (int kk = 0; kk < HDIM; kk++) {
        const float p = s[kk];
#pragma unroll
        for (int j = 0; j < NHEAD; j++)
            yacc[j] = fmaf(p, vs[kk][j], yacc[j]);
    }

    float* yout = Y + base + tid * NHEAD;
#pragma unroll
    for (int j4 = 0; j4 < 4; j4++) {
        float4 o;
        o.x = yacc[j4 * 4 + 0] * inv;
        o.y = yacc[j4 * 4 + 1] * inv;
        o.z = yacc[j4 * 4 + 2] * inv;
        o.w = yacc[j4 * 4 + 3] * inv;
        *(float4*)&yout[j4 * 4] = o;
    }
}

// ---------------------------------------------------------------------------
// Launch
// ---------------------------------------------------------------------------
extern "C" void kernel_launch(void* const* d_in, const int* in_sizes, int n_in,
                              void* d_out, int out_size)
{
    const float* x  = (const float*)d_in[0];
    const float* Wq = (const float*)d_in[1];
    const float* bq = (const float*)d_in[2];
    const float* Wk = (const float*)d_in[3];
    const float* bk = (const float*)d_in[4];
    const float* Wv = (const float*)d_in[5];
    const float* bv = (const float*)d_in[6];
    const float* Wo = (const float*)d_in[7];
    const float* bo = (const float*)d_in[8];
    float* out = (float*)d_out;

    float *Qp, *Kp, *Vp, *Yp;
    __nv_bfloat16 *Ahi, *Alo, *Whi, *Wlo;
    cudaGetSymbolAddress((void**)&Qp,  g_Q);
    cudaGetSymbolAddress((void**)&Kp,  g_K);
    cudaGetSymbolAddress((void**)&Vp,  g_V);
    cudaGetSymbolAddress((void**)&Yp,  g_Y);
    cudaGetSymbolAddress((void**)&Ahi, g_Ahi);
    cudaGetSymbolAddress((void**)&Alo, g_Alo);
    cudaGetSymbolAddress((void**)&Whi, g_Wthi);
    cudaGetSymbolAddress((void**)&Wlo, g_Wtlo);

    cudaFuncSetAttribute(gemm_mma, cudaFuncAttributeMaxDynamicSharedMemorySize,
                         SMEM_SZ);

    const size_t WS = (size_t)DIM * DIM;

    // 1) split/transpose all weights (one launch), split x
    wsplit4<<<(4 * DIM * DIM) / 256, 256>>>(Wq, Wk, Wv, Wo, Whi, Wlo);
    fsplit<<<(TOK * DIM) / 256, 256>>>(x, Ahi, Alo, TOK * DIM);

    // 2) QKV projections
    dim3 grid(DIM / TN, TOK / TM);   // (8, 128)
    gemm_mma<<<grid, 256, SMEM_SZ>>>(Ahi, Alo, Whi + 0 * WS, Wlo + 0 * WS, bq, Qp);
    gemm_mma<<<grid, 256, SMEM_SZ>>>(Ahi, Alo, Whi + 1 * WS, Wlo + 1 * WS, bk, Kp);
    gemm_mma<<<grid, 256, SMEM_SZ>>>(Ahi, Alo, Whi + 2 * WS, Wlo + 2 * WS, bv, Vp);

    // 3) attention
    attn_kernel<<<TOK, 64>>>(Qp, Kp, Vp, Yp);

    // 4) output projection
    fsplit<<<(TOK * DIM) / 256, 256>>>(Yp, Ahi, Alo, TOK * DIM);
    gemm_mma<<<grid, 256, SMEM_SZ>>>(Ahi, Alo, Whi + 3 * WS, Wlo + 3 * WS, bo, out);
}